// round 5
// baseline (speedup 1.0000x reference)
#include <cuda_runtime.h>
#include <math.h>

#define HID 64
#define CIN 4
#define HH 8
#define WW 8
#define NB 32

// Repacked masked weights (persistent device scratch; no allocation).
// g_w0p: [s][pos(4 maskA)][ic(4)][oc(64)]
// g_w12p: float4 units, unit index (((layer*2+s)*5+pos)*16+icg)*64+oc, holding ic=icg*4..+3
__device__ float  g_w0p[2 * 4 * 4 * 64];
__device__ float4 g_w12p[2 * 2 * 5 * 16 * 64];

__global__ void prep_kernel(const float* __restrict__ mu_w0, const float* __restrict__ mu_w1,
                            const float* __restrict__ mu_w2,
                            const float* __restrict__ lv_w0, const float* __restrict__ lv_w1,
                            const float* __restrict__ lv_w2) {
    int idx = blockIdx.x * blockDim.x + threadIdx.x;
    const int kyB[5] = {0, 0, 0, 1, 1};
    const int kxB[5] = {0, 1, 2, 0, 1};
    if (idx < 2048) {
        // w0 repack (mask A = first 4 positions of B list)
        int oc = idx & 63; int ic = (idx >> 6) & 3; int pos = (idx >> 8) & 3; int s = idx >> 10;
        const float* w = s ? lv_w0 : mu_w0;
        g_w0p[idx] = w[((oc * CIN + ic) * 3 + kyB[pos]) * 3 + kxB[pos]];
    }
    int j = idx - 2048;
    if (j >= 0 && j < 2 * 2 * 5 * 16 * 64 * 4) {
        int t = j;
        int e   = t & 3;  t >>= 2;
        int oc  = t & 63; t >>= 6;
        int icg = t & 15; t >>= 4;
        int pos = t % 5;  t /= 5;
        int s   = t & 1;  t >>= 1;
        int layer = t;
        int ic = icg * 4 + e;
        const float* w = layer ? (s ? lv_w2 : mu_w2) : (s ? lv_w1 : mu_w1);
        ((float*)g_w12p)[j] = w[((oc * HID + ic) * 3 + kyB[pos]) * 3 + kxB[pos]];
    }
}

__device__ __forceinline__ float eluf(float v) { return v > 0.f ? v : expm1f(v); }

__global__ __launch_bounds__(512, 1) void made_seq_kernel(
    const float* __restrict__ x,
    const float* __restrict__ mu_b0, const float* __restrict__ mu_b1,
    const float* __restrict__ mu_b2, const float* __restrict__ mu_wo,
    const float* __restrict__ mu_bo,
    const float* __restrict__ lv_b0, const float* __restrict__ lv_b1,
    const float* __restrict__ lv_b2, const float* __restrict__ lv_wo,
    const float* __restrict__ lv_bo,
    float* __restrict__ out)
{
    __shared__ float sy[CIN][HH][WW];
    __shared__ float sx[CIN][HH][WW];
    __shared__ float sh0[2][2][WW][HID];   // [stack][row parity][col][ic] — ic contiguous for LDS.128
    __shared__ float sh1[2][2][WW][HID];
    __shared__ float sh2[2][HID];
    __shared__ float spart[4][2][HID];
    __shared__ float sw0[2][4][4][HID];
    __shared__ float swo[2][CIN][HID];
    __shared__ float sb0[2][HID], sb1[2][HID], sb2[2][HID];
    __shared__ float sbo[2][CIN];
    __shared__ float smu[CIN], slv[CIN], ssum[CIN];

    const int tid = threadIdx.x;
    const int b = blockIdx.x;

    // ---- stage constants ----
    for (int i = tid; i < 2048; i += 512) ((float*)sw0)[i] = g_w0p[i];
    for (int i = tid; i < CIN * HH * WW; i += 512) {
        ((float*)sx)[i] = x[b * CIN * HH * WW + i];
        ((float*)sy)[i] = 0.f;
    }
    if (tid < HID) {
        sb0[0][tid] = mu_b0[tid]; sb1[0][tid] = mu_b1[tid]; sb2[0][tid] = mu_b2[tid];
        sb0[1][tid] = lv_b0[tid]; sb1[1][tid] = lv_b1[tid]; sb2[1][tid] = lv_b2[tid];
    }
    for (int i = tid; i < CIN * HID; i += 512) {
        ((float*)swo[0])[i] = mu_wo[i];
        ((float*)swo[1])[i] = lv_wo[i];
    }
    if (tid < CIN) { sbo[0][tid] = mu_bo[tid]; sbo[1][tid] = lv_bo[tid]; ssum[tid] = 0.f; }
    __syncthreads();

    const int dyA[4] = {-1, -1, -1, 0}, dxA[4] = {-1, 0, 1, -1};
    const int dyB[5] = {-1, -1, -1, 0, 0}, dxB[5] = {-1, 0, 1, -1, 0};

    const int sB = (tid >> 6) & 1;   // stack for conv phases
    const int ocB = tid & 63;
    const int sub = tid >> 7;        // 0..3, 16-ic slice

    for (int p = 0; p < HH * WW; ++p) {
        const int r = p >> 3, c = p & 7;

        // ---- Phase A: h0 = elu(maskA conv over y) ----
        if (tid < 128) {
            int s = tid >> 6, oc = tid & 63;
            float acc = sb0[s][oc];
            #pragma unroll
            for (int pos = 0; pos < 4; ++pos) {
                int rr = r + dyA[pos], cc = c + dxA[pos];
                if (rr >= 0 && cc >= 0 && cc < WW) {
                    #pragma unroll
                    for (int ic = 0; ic < CIN; ++ic)
                        acc += sw0[s][pos][ic][oc] * sy[ic][rr][cc];
                }
            }
            sh0[s][r & 1][c][oc] = eluf(acc);
        }
        __syncthreads();

        // ---- Phase B: h1 = elu(maskB conv over h0), layer 0 weights ----
        {
            float acc = 0.f;
            const float4* wb = g_w12p + ((0 * 2 + sB) * 5) * 16 * 64;
            #pragma unroll
            for (int pos = 0; pos < 5; ++pos) {
                int rr = r + dyB[pos], cc = c + dxB[pos];
                if (rr >= 0 && cc >= 0 && cc < WW) {
                    const float4* hv4 = (const float4*)&sh0[sB][rr & 1][cc][0];
                    #pragma unroll
                    for (int k = 0; k < 4; ++k) {
                        int icg = sub * 4 + k;
                        float4 wv = wb[(pos * 16 + icg) * 64 + ocB];
                        float4 hv = hv4[icg];
                        acc += wv.x * hv.x + wv.y * hv.y + wv.z * hv.z + wv.w * hv.w;
                    }
                }
            }
            spart[sub][sB][ocB] = acc;
        }
        __syncthreads();
        if (tid < 128) {
            int s = tid >> 6, oc = tid & 63;
            float v = spart[0][s][oc] + spart[1][s][oc] + spart[2][s][oc] + spart[3][s][oc]
                      + sb1[s][oc];
            sh1[s][r & 1][c][oc] = eluf(v);
        }
        __syncthreads();

        // ---- Phase C: h2 = elu(maskB conv over h1), layer 1 weights ----
        {
            float acc = 0.f;
            const float4* wb = g_w12p + ((1 * 2 + sB) * 5) * 16 * 64;
            #pragma unroll
            for (int pos = 0; pos < 5; ++pos) {
                int rr = r + dyB[pos], cc = c + dxB[pos];
                if (rr >= 0 && cc >= 0 && cc < WW) {
                    const float4* hv4 = (const float4*)&sh1[sB][rr & 1][cc][0];
                    #pragma unroll
                    for (int k = 0; k < 4; ++k) {
                        int icg = sub * 4 + k;
                        float4 wv = wb[(pos * 16 + icg) * 64 + ocB];
                        float4 hv = hv4[icg];
                        acc += wv.x * hv.x + wv.y * hv.y + wv.z * hv.z + wv.w * hv.w;
                    }
                }
            }
            spart[sub][sB][ocB] = acc;
        }
        __syncthreads();
        if (tid < 128) {
            int s = tid >> 6, oc = tid & 63;
            float v = spart[0][s][oc] + spart[1][s][oc] + spart[2][s][oc] + spart[3][s][oc]
                      + sb2[s][oc];
            sh2[s][oc] = eluf(v);
        }
        __syncthreads();

        // ---- Phase D: 1x1 output conv + y update ----
        if (tid < 32) {
            int grp = tid >> 2;           // 0..7 : s*4 + outc
            int s = grp >> 2, oc4 = grp & 3, ss = tid & 3;
            float acc = 0.f;
            #pragma unroll
            for (int i = 0; i < 16; ++i) {
                int ic = ss * 16 + i;
                acc += swo[s][oc4][ic] * sh2[s][ic];
            }
            acc += __shfl_xor_sync(0xffffffffu, acc, 1);
            acc += __shfl_xor_sync(0xffffffffu, acc, 2);
            if (ss == 0) {
                float v = acc + sbo[s][oc4];
                if (s == 0) smu[oc4] = v; else slv[oc4] = v;
            }
        }
        __syncthreads();
        if (tid < CIN) {
            float logstd = 0.5f * slv[tid];
            float yv = (sx[tid][r][c] - smu[tid]) / (expf(logstd) + 1e-12f);
            sy[tid][r][c] = yv;
            out[((b * CIN + tid) * HH + r) * WW + c] = yv;
            ssum[tid] += logstd;
        }
        __syncthreads();
    }

    if (tid == 0)
        out[NB * CIN * HH * WW + b] = ssum[0] + ssum[1] + ssum[2] + ssum[3];
}

extern "C" void kernel_launch(void* const* d_in, const int* in_sizes, int n_in,
                              void* d_out, int out_size) {
    (void)in_sizes; (void)n_in; (void)out_size;
    const float* x     = (const float*)d_in[0];
    const float* mu_w0 = (const float*)d_in[1];
    const float* mu_b0 = (const float*)d_in[2];
    const float* mu_w1 = (const float*)d_in[3];
    const float* mu_b1 = (const float*)d_in[4];
    const float* mu_w2 = (const float*)d_in[5];
    const float* mu_b2 = (const float*)d_in[6];
    const float* mu_wo = (const float*)d_in[7];
    const float* mu_bo = (const float*)d_in[8];
    const float* lv_w0 = (const float*)d_in[9];
    const float* lv_b0 = (const float*)d_in[10];
    const float* lv_w1 = (const float*)d_in[11];
    const float* lv_b1 = (const float*)d_in[12];
    const float* lv_w2 = (const float*)d_in[13];
    const float* lv_b2 = (const float*)d_in[14];
    const float* lv_wo = (const float*)d_in[15];
    const float* lv_bo = (const float*)d_in[16];
    float* out = (float*)d_out;

    int total = 2048 + 2 * 2 * 5 * 16 * 64 * 4;
    prep_kernel<<<(total + 255) / 256, 256>>>(mu_w0, mu_w1, mu_w2, lv_w0, lv_w1, lv_w2);
    made_seq_kernel<<<NB, 512>>>(x, mu_b0, mu_b1, mu_b2, mu_wo, mu_bo,
                                 lv_b0, lv_b1, lv_b2, lv_wo, lv_bo, out);
}

// round 8
// speedup vs baseline: 2.3863x; 2.3863x over previous
#include <cuda_runtime.h>
#include <cstdint>
#include <math.h>

#define HID 64
#define CIN 4
#define HH 8
#define WW 8
#define NB 32

// Repacked masked weights (persistent device scratch; no allocation).
// g_w0p: [s][pos(4 maskA)][ic(4)][oc(64)]
// g_w12p: float4 units, unit index (((layer*2+s)*5+pos)*16+icg)*64+oc, holding ic=icg*4..+3
__device__ float  g_w0p[2 * 4 * 4 * 64];
__device__ float4 g_w12p[2 * 2 * 5 * 16 * 64];

__global__ void prep_kernel(const float* __restrict__ mu_w0, const float* __restrict__ mu_w1,
                            const float* __restrict__ mu_w2,
                            const float* __restrict__ lv_w0, const float* __restrict__ lv_w1,
                            const float* __restrict__ lv_w2) {
    int idx = blockIdx.x * blockDim.x + threadIdx.x;
    const int kyB[5] = {0, 0, 0, 1, 1};
    const int kxB[5] = {0, 1, 2, 0, 1};
    if (idx < 2048) {
        int oc = idx & 63; int ic = (idx >> 6) & 3; int pos = (idx >> 8) & 3; int s = idx >> 10;
        const float* w = s ? lv_w0 : mu_w0;
        g_w0p[idx] = w[((oc * CIN + ic) * 3 + kyB[pos]) * 3 + kxB[pos]];
    }
    int j = idx - 2048;
    if (j >= 0 && j < 2 * 2 * 5 * 16 * 64 * 4) {
        int t = j;
        int e   = t & 3;  t >>= 2;
        int oc  = t & 63; t >>= 6;
        int icg = t & 15; t >>= 4;
        int pos = t % 5;  t /= 5;
        int s   = t & 1;  t >>= 1;
        int layer = t;
        int ic = icg * 4 + e;
        const float* w = layer ? (s ? lv_w2 : mu_w2) : (s ? lv_w1 : mu_w1);
        ((float*)g_w12p)[j] = w[((oc * HID + ic) * 3 + kyB[pos]) * 3 + kxB[pos]];
    }
}

__device__ __forceinline__ float eluf(float v) { return v > 0.f ? v : expm1f(v); }

__device__ __forceinline__ uint32_t smem_u32(const void* p) {
    uint32_t a;
    asm("{ .reg .u64 t; cvta.to.shared.u64 t, %1; cvt.u32.u64 %0, t; }" : "=r"(a) : "l"(p));
    return a;
}
__device__ __forceinline__ void st_cluster_f32(uint32_t addr, float v) {
    asm volatile("st.shared::cluster.f32 [%0], %1;" :: "r"(addr), "f"(v) : "memory");
}

// ---- dynamic smem float offsets ----
#define OFF_W12   0        // 40960 floats (layer-1/2 weights for this stack, float4 view)
#define OFF_SH0   40960    // 9*10*64 padded h0
#define OFF_SH1   46720    // 9*10*64 padded h1
#define OFF_SW0   52480    // 4*4*64
#define OFF_SWO   53504    // 4*64
#define OFF_SB0   53760
#define OFF_SB1   53824
#define OFF_SB2   53888
#define OFF_SBO   53952    // 16
#define OFF_SY    53968    // 4*9*10 = 360 (pad 368)
#define OFF_SX    54336    // 256
#define OFF_SH2   54592    // 4*64
#define OFF_SPART 54848    // 8*4*64
#define OFF_SXCHG 56896    // [stack][buf][q][ch] = 64
#define OFF_SSUM  56960    // 16
#define SMEM_FLOATS 56976
#define SMEM_BYTES (SMEM_FLOATS * 4)

__global__ void __launch_bounds__(512, 1) __cluster_dims__(2, 1, 1)
made_wave_kernel(const float* __restrict__ x,
                 const float* __restrict__ mu_b0, const float* __restrict__ mu_b1,
                 const float* __restrict__ mu_b2, const float* __restrict__ mu_wo,
                 const float* __restrict__ mu_bo,
                 const float* __restrict__ lv_b0, const float* __restrict__ lv_b1,
                 const float* __restrict__ lv_b2, const float* __restrict__ lv_wo,
                 const float* __restrict__ lv_bo,
                 float* __restrict__ out)
{
    extern __shared__ float sm[];
    const int tid = threadIdx.x;
    const int rank = blockIdx.x & 1;      // 0 = mu stack, 1 = lv stack
    const int b = blockIdx.x >> 1;

    // ---- stage weights/biases/x, zero activation buffers ----
    {
        float4* w12 = (float4*)(sm + OFF_W12);
        #pragma unroll
        for (int l = 0; l < 2; l++) {
            const float4* src = g_w12p + (l * 2 + rank) * 5120;
            float4* dst = w12 + l * 5120;
            for (int i = tid; i < 5120; i += 512) dst[i] = src[i];
        }
        for (int i = tid; i < 1024; i += 512) sm[OFF_SW0 + i] = g_w0p[rank * 1024 + i];
        const float* wo = rank ? lv_wo : mu_wo;
        const float* b0 = rank ? lv_b0 : mu_b0;
        const float* b1 = rank ? lv_b1 : mu_b1;
        const float* b2 = rank ? lv_b2 : mu_b2;
        const float* bo = rank ? lv_bo : mu_bo;
        if (tid < 256) sm[OFF_SWO + tid] = wo[tid];
        if (tid < 64) {
            sm[OFF_SB0 + tid] = b0[tid];
            sm[OFF_SB1 + tid] = b1[tid];
            sm[OFF_SB2 + tid] = b2[tid];
        }
        if (tid < 4) sm[OFF_SBO + tid] = bo[tid];
        if (tid < 256) sm[OFF_SX + tid] = x[b * 256 + tid];
        for (int i = tid; i < 5760; i += 512) { sm[OFF_SH0 + i] = 0.f; sm[OFF_SH1 + i] = 0.f; }
        for (int i = tid; i < 360; i += 512) sm[OFF_SY + i] = 0.f;
    }
    __syncthreads();

    // remote address of peer's sxchg
    uint32_t lsx = smem_u32(sm + OFF_SXCHG);
    uint32_t rsx;
    asm("mapa.shared::cluster.u32 %0, %1, %2;" : "=r"(rsx) : "r"(lsx), "r"(rank ^ 1));

    const float4* w1 = (const float4*)(sm + OFF_W12);
    const float4* w2 = w1 + 5120;

    float lsum = 0.f;

    for (int t = 0; t < 22; t++) {
        const int th = t >> 1, par = t & 1;
        // quadrant q: pixel (rq = th - q, cq = par + 2q); active iff 0 <= rq < 8
        int rq0 = th,     rq1 = th - 1, rq2 = th - 2, rq3 = th - 3;
        int re0 = ((unsigned)rq0 < 8u) ? rq0 : 0;
        int re1 = ((unsigned)rq1 < 8u) ? rq1 : 0;
        int re2 = ((unsigned)rq2 < 8u) ? rq2 : 0;
        int re3 = ((unsigned)rq3 < 8u) ? rq3 : 0;
        // padded-cell float offsets of the 4 pixel centers (in [row][col][64] layout)
        const int hb0 = ((re0 + 1) * 10 + (par + 1)) * 64;
        const int hb1 = ((re1 + 1) * 10 + (par + 3)) * 64;
        const int hb2 = ((re2 + 1) * 10 + (par + 5)) * 64;
        const int hb3 = ((re3 + 1) * 10 + (par + 7)) * 64;

        // ---- Phase A: h0 = elu(maskA conv over padded y) ----
        if (tid < 256) {
            int q = tid >> 6, oc = tid & 63;
            int rq = th - q, cq = par + 2 * q;
            if ((unsigned)rq < 8u) {
                float acc = sm[OFF_SB0 + oc];
                int yb = (rq + 1) * 10 + (cq + 1);
                #pragma unroll
                for (int ic = 0; ic < 4; ic++) {
                    const float* yp = sm + OFF_SY + ic * 90 + yb;
                    acc += sm[OFF_SW0 + (0 * 4 + ic) * 64 + oc] * yp[-11];
                    acc += sm[OFF_SW0 + (1 * 4 + ic) * 64 + oc] * yp[-10];
                    acc += sm[OFF_SW0 + (2 * 4 + ic) * 64 + oc] * yp[-9];
                    acc += sm[OFF_SW0 + (3 * 4 + ic) * 64 + oc] * yp[-1];
                }
                sm[OFF_SH0 + ((rq + 1) * 10 + (cq + 1)) * 64 + oc] = eluf(acc);
            }
        }
        __syncthreads();

        // maskB neighbor float offsets: (-1,-1),(-1,0),(-1,1),(0,-1),(0,0)
        const int OFS0 = -704, OFS1 = -640, OFS2 = -576, OFS3 = -64, OFS4 = 0;

        // ---- Phase B: layer-1 conv (weights reused across 4 pixels) ----
        {
            int oc = tid & 63, sub = tid >> 6;
            int icg0 = sub * 2;
            float ac0 = 0.f, ac1 = 0.f, ac2 = 0.f, ac3 = 0.f;
            #pragma unroll
            for (int pos = 0; pos < 5; pos++) {
                const int o = (pos == 0) ? OFS0 : (pos == 1) ? OFS1 : (pos == 2) ? OFS2
                              : (pos == 3) ? OFS3 : OFS4;
                const float4* p0 = (const float4*)(sm + OFF_SH0 + hb0 + o);
                const float4* p1 = (const float4*)(sm + OFF_SH0 + hb1 + o);
                const float4* p2 = (const float4*)(sm + OFF_SH0 + hb2 + o);
                const float4* p3 = (const float4*)(sm + OFF_SH0 + hb3 + o);
                #pragma unroll
                for (int kk = 0; kk < 2; kk++) {
                    float4 wv = w1[(pos * 16 + icg0 + kk) * 64 + oc];
                    float4 h;
                    h = p0[icg0 + kk]; ac0 += wv.x*h.x + wv.y*h.y + wv.z*h.z + wv.w*h.w;
                    h = p1[icg0 + kk]; ac1 += wv.x*h.x + wv.y*h.y + wv.z*h.z + wv.w*h.w;
                    h = p2[icg0 + kk]; ac2 += wv.x*h.x + wv.y*h.y + wv.z*h.z + wv.w*h.w;
                    h = p3[icg0 + kk]; ac3 += wv.x*h.x + wv.y*h.y + wv.z*h.z + wv.w*h.w;
                }
            }
            sm[OFF_SPART + (sub * 4 + 0) * 64 + oc] = ac0;
            sm[OFF_SPART + (sub * 4 + 1) * 64 + oc] = ac1;
            sm[OFF_SPART + (sub * 4 + 2) * 64 + oc] = ac2;
            sm[OFF_SPART + (sub * 4 + 3) * 64 + oc] = ac3;
        }
        __syncthreads();
        if (tid < 256) {
            int q = tid >> 6, oc = tid & 63;
            int rq = th - q, cq = par + 2 * q;
            if ((unsigned)rq < 8u) {
                float v = sm[OFF_SB1 + oc];
                #pragma unroll
                for (int s = 0; s < 8; s++) v += sm[OFF_SPART + (s * 4 + q) * 64 + oc];
                sm[OFF_SH1 + ((rq + 1) * 10 + (cq + 1)) * 64 + oc] = eluf(v);
            }
        }
        __syncthreads();

        // ---- Phase C: layer-2 conv ----
        {
            int oc = tid & 63, sub = tid >> 6;
            int icg0 = sub * 2;
            float ac0 = 0.f, ac1 = 0.f, ac2 = 0.f, ac3 = 0.f;
            #pragma unroll
            for (int pos = 0; pos < 5; pos++) {
                const int o = (pos == 0) ? OFS0 : (pos == 1) ? OFS1 : (pos == 2) ? OFS2
                              : (pos == 3) ? OFS3 : OFS4;
                const float4* p0 = (const float4*)(sm + OFF_SH1 + hb0 + o);
                const float4* p1 = (const float4*)(sm + OFF_SH1 + hb1 + o);
                const float4* p2 = (const float4*)(sm + OFF_SH1 + hb2 + o);
                const float4* p3 = (const float4*)(sm + OFF_SH1 + hb3 + o);
                #pragma unroll
                for (int kk = 0; kk < 2; kk++) {
                    float4 wv = w2[(pos * 16 + icg0 + kk) * 64 + oc];
                    float4 h;
                    h = p0[icg0 + kk]; ac0 += wv.x*h.x + wv.y*h.y + wv.z*h.z + wv.w*h.w;
                    h = p1[icg0 + kk]; ac1 += wv.x*h.x + wv.y*h.y + wv.z*h.z + wv.w*h.w;
                    h = p2[icg0 + kk]; ac2 += wv.x*h.x + wv.y*h.y + wv.z*h.z + wv.w*h.w;
                    h = p3[icg0 + kk]; ac3 += wv.x*h.x + wv.y*h.y + wv.z*h.z + wv.w*h.w;
                }
            }
            sm[OFF_SPART + (sub * 4 + 0) * 64 + oc] = ac0;
            sm[OFF_SPART + (sub * 4 + 1) * 64 + oc] = ac1;
            sm[OFF_SPART + (sub * 4 + 2) * 64 + oc] = ac2;
            sm[OFF_SPART + (sub * 4 + 3) * 64 + oc] = ac3;
        }
        __syncthreads();
        if (tid < 256) {
            int q = tid >> 6, oc = tid & 63;
            int rq = th - q;
            if ((unsigned)rq < 8u) {
                float v = sm[OFF_SB2 + oc];
                #pragma unroll
                for (int s = 0; s < 8; s++) v += sm[OFF_SPART + (s * 4 + q) * 64 + oc];
                sm[OFF_SH2 + q * 64 + oc] = eluf(v);
            }
        }
        __syncthreads();

        // ---- Phase D: 1x1 output conv, write result to own + peer sxchg ----
        if (tid < 128) {
            int q = tid >> 5, lane = tid & 31, ch = lane >> 3, ss = lane & 7;
            float acc = 0.f;
            #pragma unroll
            for (int i = 0; i < 8; i++) {
                int ic = ss * 8 + i;
                acc += sm[OFF_SWO + ch * 64 + ic] * sm[OFF_SH2 + q * 64 + ic];
            }
            acc += __shfl_xor_sync(0xffffffffu, acc, 1);
            acc += __shfl_xor_sync(0xffffffffu, acc, 2);
            acc += __shfl_xor_sync(0xffffffffu, acc, 4);
            int rq = th - q;
            if (ss == 0 && (unsigned)rq < 8u) {
                float v = acc + sm[OFF_SBO + ch];
                int idx = rank * 32 + par * 16 + q * 4 + ch;
                sm[OFF_SXCHG + idx] = v;
                st_cluster_f32(rsx + idx * 4, v);
            }
        }

        // cluster barrier: publishes remote sxchg stores (release/acquire) and
        // doubles as the CTA-wide barrier for this step's exchange.
        asm volatile("barrier.cluster.arrive.aligned;" ::: "memory");
        asm volatile("barrier.cluster.wait.aligned;" ::: "memory");

        // ---- y update (both CTAs compute y locally; rank 0 writes gmem) ----
        if (tid < 16) {
            int q = tid >> 2, ch = tid & 3;
            int rq = th - q, cq = par + 2 * q;
            if ((unsigned)rq < 8u) {
                float mu = sm[OFF_SXCHG + par * 16 + q * 4 + ch];
                float lv = sm[OFF_SXCHG + 32 + par * 16 + q * 4 + ch];
                float logstd = 0.5f * lv;
                float yv = (sm[OFF_SX + (ch * 8 + rq) * 8 + cq] - mu) / (expf(logstd) + 1e-12f);
                sm[OFF_SY + ch * 90 + (rq + 1) * 10 + (cq + 1)] = yv;
                if (rank == 0) out[((b * 4 + ch) * 8 + rq) * 8 + cq] = yv;
                lsum += logstd;
            }
        }
        __syncthreads();
    }

    if (tid < 16) sm[OFF_SSUM + tid] = lsum;
    __syncthreads();
    if (rank == 0 && tid == 0) {
        float s = 0.f;
        #pragma unroll
        for (int i = 0; i < 16; i++) s += sm[OFF_SSUM + i];
        out[NB * CIN * HH * WW + b] = s;
    }
}

extern "C" void kernel_launch(void* const* d_in, const int* in_sizes, int n_in,
                              void* d_out, int out_size) {
    (void)in_sizes; (void)n_in; (void)out_size;
    const float* x     = (const float*)d_in[0];
    const float* mu_w0 = (const float*)d_in[1];
    const float* mu_b0 = (const float*)d_in[2];
    const float* mu_w1 = (const float*)d_in[3];
    const float* mu_b1 = (const float*)d_in[4];
    const float* mu_w2 = (const float*)d_in[5];
    const float* mu_b2 = (const float*)d_in[6];
    const float* mu_wo = (const float*)d_in[7];
    const float* mu_bo = (const float*)d_in[8];
    const float* lv_w0 = (const float*)d_in[9];
    const float* lv_b0 = (const float*)d_in[10];
    const float* lv_w1 = (const float*)d_in[11];
    const float* lv_b1 = (const float*)d_in[12];
    const float* lv_w2 = (const float*)d_in[13];
    const float* lv_b2 = (const float*)d_in[14];
    const float* lv_wo = (const float*)d_in[15];
    const float* lv_bo = (const float*)d_in[16];
    float* out = (float*)d_out;

    cudaFuncSetAttribute(made_wave_kernel,
                         cudaFuncAttributeMaxDynamicSharedMemorySize, SMEM_BYTES);

    int total = 2048 + 2 * 2 * 5 * 16 * 64 * 4;
    prep_kernel<<<(total + 255) / 256, 256>>>(mu_w0, mu_w1, mu_w2, lv_w0, lv_w1, lv_w2);
    made_wave_kernel<<<2 * NB, 512, SMEM_BYTES>>>(x, mu_b0, mu_b1, mu_b2, mu_wo, mu_bo,
                                                  lv_b0, lv_b1, lv_b2, lv_wo, lv_bo, out);
}